// round 12
// baseline (speedup 1.0000x reference)
#include <cuda_runtime.h>
#include <cstdint>

// LocalConvolution via warp-level bf16 mma.sync (sm_80+ base ISA; tcgen05 is
// gated behind compute_103a which this harness's PTX target does not have).
// out[b,o,i,j] = sum_{c,u,v} x[b,c,i+u,j+v] * w[i,j,o,c,u,v]
// B=64, C=64, H=W=32, ROWS=COLS=28, O=128, KH=KW=5.
//
// One CTA per pixel: D[o=128, b=64], K=1600 in 32 chunks of 2 channels
// (K=64 bf16 per chunk; k-slots 25..31 and 57..63 zero-padded).
// fp32 emulated by 2-term bf16 split: W*X ~= Whi*Xhi + Whi*Xlo + Wlo*Xhi.
// Fragments loaded with plain LDS.32 from sw128-swizzled tiles (conflict-free;
// swizzle folds the row bits into bank bits - verified all 32 lanes distinct).
// Audited 5x: fragment maps, straddle remap, pad safety, coalescing, sync
// legality, L2/DRAM traffic budgets.

#define CH    64
#define COLS  28
#define OUT_O 128
#define NPIX  784
#define KTOT  1600

// smem tile byte offsets (4 tiles = exactly 48KB static)
#define WHI 0u
#define WLO 16384u
#define XHI 32768u
#define XLO 40960u

static __device__ __forceinline__ unsigned swz(unsigned off) {
    return off ^ ((off >> 3) & 0x70u);
}

static __device__ __forceinline__ unsigned lds32(const char* p) {
    return *(const unsigned*)p;
}

// split f into bf16 hi (exact truncation) and bf16 lo (rounded residual)
static __device__ __forceinline__ void split1(float f, unsigned short& h,
                                              unsigned short& l) {
    unsigned u = __float_as_uint(f);
    h = (unsigned short)(u >> 16);
    float lo = f - __uint_as_float(u & 0xFFFF0000u);
    asm("cvt.rn.bf16.f32 %0, %1;" : "=h"(l) : "f"(lo));
}

static __device__ __forceinline__ void mma16816(float* c, const unsigned* a,
                                                unsigned b0, unsigned b1) {
    asm volatile(
        "mma.sync.aligned.m16n8k16.row.col.f32.bf16.bf16.f32 "
        "{%0,%1,%2,%3}, {%4,%5,%6,%7}, {%8,%9}, {%0,%1,%2,%3};"
        : "+f"(c[0]), "+f"(c[1]), "+f"(c[2]), "+f"(c[3])
        : "r"(a[0]), "r"(a[1]), "r"(a[2]), "r"(a[3]), "r"(b0), "r"(b1));
}

extern "C" __global__ void __launch_bounds__(128, 4)
lconv_mma(const float* __restrict__ x,
          const float* __restrict__ w,
          float* __restrict__ out)
{
    __shared__ char sm[49152];
    const int t    = threadIdx.x;
    const int lane = t & 31;
    const int wrp  = t >> 5;
    const int p    = blockIdx.x;
    const int pi   = p / COLS;
    const int pj   = p % COLS;
    const int g    = lane >> 2;    // fragment group row/col 0..7
    const int tq   = lane & 3;     // thread-in-group 0..3

    // Zero all tiles once: pad k-slots (25..31, 57..63) stay zero forever.
    for (int i = t; i < 49152 / 4; i += 128) ((unsigned*)sm)[i] = 0;
    __syncthreads();

    float acc[2][8][4];
#pragma unroll
    for (int mt = 0; mt < 2; mt++)
#pragma unroll
        for (int nt = 0; nt < 8; nt++)
#pragma unroll
            for (int r = 0; r < 4; r++) acc[mt][nt][r] = 0.f;

    const float* wbase = w + (size_t)p * OUT_O * KTOT;
    const int    xrow  = t & 63;        // batch row this thread stages
    const int    xz    = t >> 6;        // which channel of the chunk (0/1)

    for (int ch2 = 0; ch2 < 32; ch2++) {
        const int c0 = 2 * ch2;

        // ---- stage W chunk: coalesced float2 loads, split, STS.16 ----
        // pair index pe = t + 128*i -> adjacent threads read adjacent gmem.
        const float* wc = wbase + c0 * 25;
#pragma unroll
        for (int i = 0; i < 25; i++) {
            int pe = t + 128 * i;
            int o  = pe / 25;
            int j  = pe - 25 * o;
            int q0 = 2 * j;                       // element index even -> 8B aligned
            float2 f = *(const float2*)(wc + (size_t)o * KTOT + q0);
            int ks0 = (q0     < 25) ? q0     : q0 + 7;   // z*32 + k
            int ks1 = (q0 + 1 < 25) ? q0 + 1 : q0 + 8;
            unsigned short h, l;
            split1(f.x, h, l);
            unsigned off0 = swz((unsigned)(o * 128 + ks0 * 2));
            *(unsigned short*)(sm + WHI + off0) = h;
            *(unsigned short*)(sm + WLO + off0) = l;
            split1(f.y, h, l);
            unsigned off1 = swz((unsigned)(o * 128 + ks1 * 2));
            *(unsigned short*)(sm + WHI + off1) = h;
            *(unsigned short*)(sm + WLO + off1) = l;
        }

        // ---- stage X chunk ----
        const float* xc = x + (((size_t)(xrow * CH + c0 + xz)) * 32 + pi) * 32 + pj;
#pragma unroll
        for (int k0 = 0; k0 < 25; k0++) {
            int u = k0 / 5, v = k0 - u * 5;
            float f = xc[u * 32 + v];
            unsigned short h, l;
            split1(f, h, l);
            unsigned off = swz((unsigned)(xrow * 128 + (xz * 32 + k0) * 2));
            *(unsigned short*)(sm + XHI + off) = h;
            *(unsigned short*)(sm + XLO + off) = l;
        }
        __syncthreads();                  // tiles ready

        // ---- compute: 4 K16-steps x (2 m-tiles x 8 n-tiles x 3 terms) ----
#pragma unroll
        for (int kk = 0; kk < 4; kk++) {
            unsigned ahi[2][4], alo[2][4];
#pragma unroll
            for (int mt = 0; mt < 2; mt++) {
                unsigned r = (unsigned)((wrp * 32 + mt * 16 + g) * 128
                                        + kk * 32 + tq * 4);
                ahi[mt][0] = lds32(sm + WHI + swz(r));
                ahi[mt][1] = lds32(sm + WHI + swz(r + 1024));
                ahi[mt][2] = lds32(sm + WHI + swz(r + 16));
                ahi[mt][3] = lds32(sm + WHI + swz(r + 1040));
                alo[mt][0] = lds32(sm + WLO + swz(r));
                alo[mt][1] = lds32(sm + WLO + swz(r + 1024));
                alo[mt][2] = lds32(sm + WLO + swz(r + 16));
                alo[mt][3] = lds32(sm + WLO + swz(r + 1040));
            }
#pragma unroll
            for (int nt = 0; nt < 8; nt++) {
                unsigned rb = (unsigned)((nt * 8 + g) * 128 + kk * 32 + tq * 4);
                unsigned bh0 = lds32(sm + XHI + swz(rb));
                unsigned bh1 = lds32(sm + XHI + swz(rb + 16));
                unsigned bl0 = lds32(sm + XLO + swz(rb));
                unsigned bl1 = lds32(sm + XLO + swz(rb + 16));
#pragma unroll
                for (int mt = 0; mt < 2; mt++) {
                    mma16816(acc[mt][nt], ahi[mt], bh0, bh1);   // hi*hi
                    mma16816(acc[mt][nt], ahi[mt], bl0, bl1);   // hi*lo
                    mma16816(acc[mt][nt], alo[mt], bh0, bh1);   // lo*hi
                }
            }
        }
        __syncthreads();                  // all reads done before next stage
    }

    // ---- epilogue: D fragment -> out[((b*128+o)*784)+p] ----
#pragma unroll
    for (int mt = 0; mt < 2; mt++) {
        int o0 = wrp * 32 + mt * 16 + g;
#pragma unroll
        for (int nt = 0; nt < 8; nt++) {
            int b0 = nt * 8 + 2 * tq;
            const float* c = acc[mt][nt];
            asm volatile("st.global.cs.f32 [%0], %1;" ::
                "l"(out + ((size_t)b0       * OUT_O + o0    ) * NPIX + p), "f"(c[0]));
            asm volatile("st.global.cs.f32 [%0], %1;" ::
                "l"(out + ((size_t)(b0 + 1) * OUT_O + o0    ) * NPIX + p), "f"(c[1]));
            asm volatile("st.global.cs.f32 [%0], %1;" ::
                "l"(out + ((size_t)b0       * OUT_O + o0 + 8) * NPIX + p), "f"(c[2]));
            asm volatile("st.global.cs.f32 [%0], %1;" ::
                "l"(out + ((size_t)(b0 + 1) * OUT_O + o0 + 8) * NPIX + p), "f"(c[3]));
        }
    }
}

extern "C" void kernel_launch(void* const* d_in, const int* in_sizes, int n_in,
                              void* d_out, int out_size) {
    const float* x = (const float*)d_in[0];   // [64,64,32,32]
    const float* w = (const float*)d_in[1];   // [28,28,128,64,5,5]
    float* out = (float*)d_out;               // [64,128,28,28]
    (void)in_sizes; (void)n_in; (void)out_size;
    lconv_mma<<<NPIX, 128>>>(x, w, out);
}